// round 14
// baseline (speedup 1.0000x reference)
#include <cuda_runtime.h>
#include <cuda_bf16.h>

#define EPS_SIGN 1e-8f
#define EPS_NORM 1e-9f

// Padded xyz as float4: each node gather = ONE LDG.128.
#define XYZ4_CAP 131072
__device__ float4 g_xyz4[XYZ4_CAP];

// Vectorized repack: thread j handles nodes 4j..4j+3 via 3 float4 loads.
__global__ __launch_bounds__(256)
void repack_xyz4_kernel(const float4* __restrict__ xyz4, int N4, int N)
{
    int j = blockIdx.x * blockDim.x + threadIdx.x;
    if (j < N4) {
        float4 f0 = xyz4[3*j + 0];   // x0 y0 z0 x1
        float4 f1 = xyz4[3*j + 1];   // y1 z1 x2 y2
        float4 f2 = xyz4[3*j + 2];   // z2 x3 y3 z3
        g_xyz4[4*j + 0] = make_float4(f0.x, f0.y, f0.z, 0.0f);
        g_xyz4[4*j + 1] = make_float4(f0.w, f1.x, f1.y, 0.0f);
        g_xyz4[4*j + 2] = make_float4(f1.z, f1.w, f2.x, 0.0f);
        g_xyz4[4*j + 3] = make_float4(f2.y, f2.z, f2.w, 0.0f);
    } else if (j == N4) {
        const float* xyz = (const float*)xyz4;
        for (int i = 4 * N4; i < N; i++)
            g_xyz4[i] = make_float4(xyz[3*i+0], xyz[3*i+1], xyz[3*i+2], 0.0f);
    }
}

__device__ __forceinline__ void edge_math(float4 a, float4 b,
                                          float cx, float cy, float cz,
                                          float& vx, float& vy, float& vz,
                                          float& dis)
{
    float dx = a.x - b.x, dy = a.y - b.y, dz = a.z - b.z;
    float ax = fabsf(dx), ay = fabsf(dy), az = fabsf(dz);

    float mx = fminf(cx - ax, ax);
    float my = fminf(cy - ay, ay);
    float mz = fminf(cz - az, az);

    float k2x = (fabsf(mx) == ax) ? 1.0f : -1.0f;
    float k2y = (fabsf(my) == ay) ? 1.0f : -1.0f;
    float k2z = (fabsf(mz) == az) ? 1.0f : -1.0f;

    float sx = (dx + EPS_SIGN >= 0.0f) ? 1.0f : -1.0f;
    float sy = (dy + EPS_SIGN >= 0.0f) ? 1.0f : -1.0f;
    float sz = (dz + EPS_SIGN >= 0.0f) ? 1.0f : -1.0f;

    vx = mx * (k2x * sx);
    vy = my * (k2y * sy);
    vz = mz * (k2z * sz);

    float ex = dx + EPS_NORM, ey = dy + EPS_NORM, ez = dz + EPS_NORM;
    dis = sqrtf(ex*ex + ey*ey + ez*ez);
}

// Persistent grid-stride version of the R6 kernel (best measured geometry):
// 2 edges/thread warp-strided (e, e+32), shuffle-coalesced vec stores.
// One resident wave loops over 64-edge chunks -> no wave-transition drain;
// consecutive chunks are independent, so the LSU queue stays full across
// the loop back-edge.
__global__ __launch_bounds__(256)
void edge_min_image_kernel(const int*   __restrict__ src,
                           const int*   __restrict__ dst,
                           const float* __restrict__ cell,
                           float* __restrict__ out_dis,
                           float* __restrict__ out_vec,
                           int E)
{
    const float cx = __ldg(&cell[0]);
    const float cy = __ldg(&cell[1]);
    const float cz = __ldg(&cell[2]);

    int lane       = threadIdx.x & 31;
    int gwarp      = (blockIdx.x * blockDim.x + threadIdx.x) >> 5;
    int nwarps     = (gridDim.x * blockDim.x) >> 5;
    int chunk_step = nwarps << 6;                  // 64 edges per warp-chunk
    int full_limit = E & ~63;                      // last multiple of 64

    int base = gwarp << 6;

    // ---- hot loop: full 64-edge chunks only ----
    for (; base + 64 <= E; base += chunk_step) {
        int e0 = base + lane;
        int e1 = base + 32 + lane;

        int s0 = __ldg(&src[e0]);
        int s1 = __ldg(&src[e1]);
        int d0 = __ldg(&dst[e0]);
        int d1 = __ldg(&dst[e1]);

        float4 a0 = __ldg(&g_xyz4[s0]);
        float4 a1 = __ldg(&g_xyz4[s1]);
        float4 b0 = __ldg(&g_xyz4[d0]);
        float4 b1 = __ldg(&g_xyz4[d1]);

        float vx0, vy0, vz0, dis0, vx1, vy1, vz1, dis1;
        edge_math(a0, b0, cx, cy, cz, vx0, vy0, vz0, dis0);
        edge_math(a1, b1, cx, cy, cz, vx1, vy1, vz1, dis1);

        out_dis[e0] = dis0;
        out_dis[e1] = dis1;

        float* bp = out_vec + 3 * base;  // 192-float span
        #pragma unroll
        for (int p = 0; p < 3; p++) {    // slot 0: floats [0,96)
            int g  = p * 32 + lane;
            int sl = g / 3;
            int c  = g - 3 * sl;
            float t0 = __shfl_sync(0xffffffffu, vx0, sl);
            float t1 = __shfl_sync(0xffffffffu, vy0, sl);
            float t2 = __shfl_sync(0xffffffffu, vz0, sl);
            bp[g] = (c == 0) ? t0 : ((c == 1) ? t1 : t2);
        }
        #pragma unroll
        for (int p = 0; p < 3; p++) {    // slot 1: floats [96,192)
            int g  = p * 32 + lane;
            int sl = g / 3;
            int c  = g - 3 * sl;
            float t0 = __shfl_sync(0xffffffffu, vx1, sl);
            float t1 = __shfl_sync(0xffffffffu, vy1, sl);
            float t2 = __shfl_sync(0xffffffffu, vz1, sl);
            bp[96 + g] = (c == 0) ? t0 : ((c == 1) ? t1 : t2);
        }
    }

    // ---- tail chunk (at most one warp lands here) ----
    if (base == full_limit && base < E) {
        #pragma unroll
        for (int k = 0; k < 2; k++) {
            int e = base + 32 * k + lane;
            if (e < E) {
                float4 a = __ldg(&g_xyz4[__ldg(&src[e])]);
                float4 b = __ldg(&g_xyz4[__ldg(&dst[e])]);
                float vx, vy, vz, dis;
                edge_math(a, b, cx, cy, cz, vx, vy, vz, dis);
                out_dis[e] = dis;
                float* vp = out_vec + 3 * e;
                vp[0] = vx; vp[1] = vy; vp[2] = vz;
            }
        }
    }
}

// Fallback (N > scratch capacity): scalar-gather path, always correct.
__global__ __launch_bounds__(256)
void edge_min_image_fallback(const float* __restrict__ xyz,
                             const int*   __restrict__ src,
                             const int*   __restrict__ dst,
                             const float* __restrict__ cell,
                             float* __restrict__ out_dis,
                             float* __restrict__ out_vec,
                             int E)
{
    const float cx = __ldg(&cell[0]);
    const float cy = __ldg(&cell[1]);
    const float cz = __ldg(&cell[2]);

    int e = blockIdx.x * blockDim.x + threadIdx.x;
    if (e >= E) return;

    int si = src[e], di = dst[e];
    float dx = xyz[3*si+0] - xyz[3*di+0];
    float dy = xyz[3*si+1] - xyz[3*di+1];
    float dz = xyz[3*si+2] - xyz[3*di+2];

    float ax = fabsf(dx), ay = fabsf(dy), az = fabsf(dz);
    float mx = fminf(cx - ax, ax);
    float my = fminf(cy - ay, ay);
    float mz = fminf(cz - az, az);
    float k2x = (fabsf(mx) == ax) ? 1.0f : -1.0f;
    float k2y = (fabsf(my) == ay) ? 1.0f : -1.0f;
    float k2z = (fabsf(mz) == az) ? 1.0f : -1.0f;
    float sx = (dx + EPS_SIGN >= 0.0f) ? 1.0f : -1.0f;
    float sy = (dy + EPS_SIGN >= 0.0f) ? 1.0f : -1.0f;
    float sz = (dz + EPS_SIGN >= 0.0f) ? 1.0f : -1.0f;

    out_vec[3*e+0] = mx * (k2x * sx);
    out_vec[3*e+1] = my * (k2y * sy);
    out_vec[3*e+2] = mz * (k2z * sz);

    float ex = dx + EPS_NORM, ey = dy + EPS_NORM, ez = dz + EPS_NORM;
    out_dis[e] = sqrtf(ex*ex + ey*ey + ez*ez);
}

extern "C" void kernel_launch(void* const* d_in, const int* in_sizes, int n_in,
                              void* d_out, int out_size)
{
    const float* xyz  = (const float*)d_in[0];
    const int*   src  = (const int*)  d_in[1];
    const int*   dst  = (const int*)  d_in[2];
    const float* cell = (const float*)d_in[3];

    int N = in_sizes[0] / 3;   // xyz rows
    int E = in_sizes[1];       // number of edges

    float* out_dis = (float*)d_out;   // [E]
    float* out_vec = out_dis + E;     // [E,3] row-major

    const int t = 256;
    if (N <= XYZ4_CAP) {
        int N4 = N / 4;
        int rthreads = N4 + 1;
        repack_xyz4_kernel<<<(rthreads + t - 1) / t, t>>>(
            (const float4*)xyz, N4, N);
        // One resident wave: 148 SMs x 8 CTAs of 256 threads.
        int blocks = 1184;
        int warps_needed = (E + 63) / 64;
        int max_blocks   = (warps_needed + 7) / 8;
        if (blocks > max_blocks) blocks = max_blocks;
        edge_min_image_kernel<<<blocks, t>>>(src, dst, cell,
                                             out_dis, out_vec, E);
    } else {
        edge_min_image_fallback<<<(E + t - 1) / t, t>>>(xyz, src, dst, cell,
                                                        out_dis, out_vec, E);
    }
}

// round 15
// speedup vs baseline: 1.0551x; 1.0551x over previous
#include <cuda_runtime.h>
#include <cuda_bf16.h>

#define EPS_SIGN 1e-8f
#define EPS_NORM 1e-9f

// Padded xyz as float4: each node gather = ONE LDG.128.
#define XYZ4_CAP 131072
__device__ float4 g_xyz4[XYZ4_CAP];

// Vectorized repack: thread j handles nodes 4j..4j+3 via 3 float4 loads.
__global__ __launch_bounds__(256)
void repack_xyz4_kernel(const float4* __restrict__ xyz4, int N4, int N)
{
    int j = blockIdx.x * blockDim.x + threadIdx.x;
    if (j < N4) {
        float4 f0 = xyz4[3*j + 0];   // x0 y0 z0 x1
        float4 f1 = xyz4[3*j + 1];   // y1 z1 x2 y2
        float4 f2 = xyz4[3*j + 2];   // z2 x3 y3 z3
        g_xyz4[4*j + 0] = make_float4(f0.x, f0.y, f0.z, 0.0f);
        g_xyz4[4*j + 1] = make_float4(f0.w, f1.x, f1.y, 0.0f);
        g_xyz4[4*j + 2] = make_float4(f1.z, f1.w, f2.x, 0.0f);
        g_xyz4[4*j + 3] = make_float4(f2.y, f2.z, f2.w, 0.0f);
    } else if (j == N4) {
        const float* xyz = (const float*)xyz4;
        for (int i = 4 * N4; i < N; i++)
            g_xyz4[i] = make_float4(xyz[3*i+0], xyz[3*i+1], xyz[3*i+2], 0.0f);
    }
}

// Streaming gather: L1::no_allocate skips the L1 line fill/evict on the
// (guaranteed-miss) random gather — the 2MB table thrashes 228KB L1, so
// every fill is wasted l1tex work competing with demand wavefronts.
__device__ __forceinline__ float4 gather_na(const float4* __restrict__ p)
{
    float4 r;
    asm("ld.global.nc.L1::no_allocate.v4.f32 {%0,%1,%2,%3}, [%4];"
        : "=f"(r.x), "=f"(r.y), "=f"(r.z), "=f"(r.w)
        : "l"(p));
    return r;
}

__device__ __forceinline__ void edge_math(float4 a, float4 b,
                                          float cx, float cy, float cz,
                                          float& vx, float& vy, float& vz,
                                          float& dis)
{
    float dx = a.x - b.x, dy = a.y - b.y, dz = a.z - b.z;
    float ax = fabsf(dx), ay = fabsf(dy), az = fabsf(dz);

    float mx = fminf(cx - ax, ax);
    float my = fminf(cy - ay, ay);
    float mz = fminf(cz - az, az);

    float k2x = (fabsf(mx) == ax) ? 1.0f : -1.0f;
    float k2y = (fabsf(my) == ay) ? 1.0f : -1.0f;
    float k2z = (fabsf(mz) == az) ? 1.0f : -1.0f;

    float sx = (dx + EPS_SIGN >= 0.0f) ? 1.0f : -1.0f;
    float sy = (dy + EPS_SIGN >= 0.0f) ? 1.0f : -1.0f;
    float sz = (dz + EPS_SIGN >= 0.0f) ? 1.0f : -1.0f;

    vx = mx * (k2x * sx);
    vy = my * (k2y * sy);
    vz = mz * (k2z * sz);

    float ex = dx + EPS_NORM, ey = dy + EPS_NORM, ez = dz + EPS_NORM;
    dis = sqrtf(ex*ex + ey*ey + ez*ez);
}

// R6 geometry (best measured): 2 edges/thread warp-strided (e, e+32),
// shuffle-coalesced vec stores (3 wf / 32 edges), classic grid.
// Only change vs R6: gathers use L1::no_allocate.
__global__ __launch_bounds__(256)
void edge_min_image_kernel(const int*   __restrict__ src,
                           const int*   __restrict__ dst,
                           const float* __restrict__ cell,
                           float* __restrict__ out_dis,
                           float* __restrict__ out_vec,
                           int E)
{
    int tid  = blockIdx.x * blockDim.x + threadIdx.x;
    int lane = threadIdx.x & 31;
    int base = ((tid >> 5) << 6);        // 64 edges per warp
    if (base >= E) return;

    const float cx = __ldg(&cell[0]);
    const float cy = __ldg(&cell[1]);
    const float cz = __ldg(&cell[2]);

    int e0 = base + lane;
    int e1 = base + 32 + lane;

    if (base + 64 <= E) {
        int s0 = __ldg(&src[e0]);
        int s1 = __ldg(&src[e1]);
        int d0 = __ldg(&dst[e0]);
        int d1 = __ldg(&dst[e1]);

        float4 a0 = gather_na(g_xyz4 + s0);
        float4 a1 = gather_na(g_xyz4 + s1);
        float4 b0 = gather_na(g_xyz4 + d0);
        float4 b1 = gather_na(g_xyz4 + d1);

        float vx0, vy0, vz0, dis0, vx1, vy1, vz1, dis1;
        edge_math(a0, b0, cx, cy, cz, vx0, vy0, vz0, dis0);
        edge_math(a1, b1, cx, cy, cz, vx1, vy1, vz1, dis1);

        out_dis[e0] = dis0;
        out_dis[e1] = dis1;

        float* bp = out_vec + 3 * base;  // 192-float span
        #pragma unroll
        for (int p = 0; p < 3; p++) {    // slot 0: floats [0,96)
            int g  = p * 32 + lane;
            int sl = g / 3;
            int c  = g - 3 * sl;
            float t0 = __shfl_sync(0xffffffffu, vx0, sl);
            float t1 = __shfl_sync(0xffffffffu, vy0, sl);
            float t2 = __shfl_sync(0xffffffffu, vz0, sl);
            bp[g] = (c == 0) ? t0 : ((c == 1) ? t1 : t2);
        }
        #pragma unroll
        for (int p = 0; p < 3; p++) {    // slot 1: floats [96,192)
            int g  = p * 32 + lane;
            int sl = g / 3;
            int c  = g - 3 * sl;
            float t0 = __shfl_sync(0xffffffffu, vx1, sl);
            float t1 = __shfl_sync(0xffffffffu, vy1, sl);
            float t2 = __shfl_sync(0xffffffffu, vz1, sl);
            bp[96 + g] = (c == 0) ? t0 : ((c == 1) ? t1 : t2);
        }
    } else {
        // tail warp: per-edge scalar
        #pragma unroll
        for (int k = 0; k < 2; k++) {
            int e = base + 32 * k + lane;
            if (e < E) {
                float4 a = gather_na(g_xyz4 + __ldg(&src[e]));
                float4 b = gather_na(g_xyz4 + __ldg(&dst[e]));
                float vx, vy, vz, dis;
                edge_math(a, b, cx, cy, cz, vx, vy, vz, dis);
                out_dis[e] = dis;
                float* vp = out_vec + 3 * e;
                vp[0] = vx; vp[1] = vy; vp[2] = vz;
            }
        }
    }
}

// Fallback (N > scratch capacity): scalar-gather path, always correct.
__global__ __launch_bounds__(256)
void edge_min_image_fallback(const float* __restrict__ xyz,
                             const int*   __restrict__ src,
                             const int*   __restrict__ dst,
                             const float* __restrict__ cell,
                             float* __restrict__ out_dis,
                             float* __restrict__ out_vec,
                             int E)
{
    const float cx = __ldg(&cell[0]);
    const float cy = __ldg(&cell[1]);
    const float cz = __ldg(&cell[2]);

    int e = blockIdx.x * blockDim.x + threadIdx.x;
    if (e >= E) return;

    int si = src[e], di = dst[e];
    float dx = xyz[3*si+0] - xyz[3*di+0];
    float dy = xyz[3*si+1] - xyz[3*di+1];
    float dz = xyz[3*si+2] - xyz[3*di+2];

    float ax = fabsf(dx), ay = fabsf(dy), az = fabsf(dz);
    float mx = fminf(cx - ax, ax);
    float my = fminf(cy - ay, ay);
    float mz = fminf(cz - az, az);
    float k2x = (fabsf(mx) == ax) ? 1.0f : -1.0f;
    float k2y = (fabsf(my) == ay) ? 1.0f : -1.0f;
    float k2z = (fabsf(mz) == az) ? 1.0f : -1.0f;
    float sx = (dx + EPS_SIGN >= 0.0f) ? 1.0f : -1.0f;
    float sy = (dy + EPS_SIGN >= 0.0f) ? 1.0f : -1.0f;
    float sz = (dz + EPS_SIGN >= 0.0f) ? 1.0f : -1.0f;

    out_vec[3*e+0] = mx * (k2x * sx);
    out_vec[3*e+1] = my * (k2y * sy);
    out_vec[3*e+2] = mz * (k2z * sz);

    float ex = dx + EPS_NORM, ey = dy + EPS_NORM, ez = dz + EPS_NORM;
    out_dis[e] = sqrtf(ex*ex + ey*ey + ez*ez);
}

extern "C" void kernel_launch(void* const* d_in, const int* in_sizes, int n_in,
                              void* d_out, int out_size)
{
    const float* xyz  = (const float*)d_in[0];
    const int*   src  = (const int*)  d_in[1];
    const int*   dst  = (const int*)  d_in[2];
    const float* cell = (const float*)d_in[3];

    int N = in_sizes[0] / 3;   // xyz rows
    int E = in_sizes[1];       // number of edges

    float* out_dis = (float*)d_out;   // [E]
    float* out_vec = out_dis + E;     // [E,3] row-major

    const int t = 256;
    if (N <= XYZ4_CAP) {
        int N4 = N / 4;
        int rthreads = N4 + 1;
        repack_xyz4_kernel<<<(rthreads + t - 1) / t, t>>>(
            (const float4*)xyz, N4, N);
        int warps  = (E + 63) / 64;      // 64 edges per warp
        int blocks = (warps + 7) / 8;    // 8 warps per block
        edge_min_image_kernel<<<blocks, t>>>(src, dst, cell,
                                             out_dis, out_vec, E);
    } else {
        edge_min_image_fallback<<<(E + t - 1) / t, t>>>(xyz, src, dst, cell,
                                                        out_dis, out_vec, E);
    }
}

// round 16
// speedup vs baseline: 1.1171x; 1.0588x over previous
#include <cuda_runtime.h>
#include <cuda_bf16.h>

#define EPS_SIGN 1e-8f
#define EPS_NORM 1e-9f

// Padded xyz as float4: each node gather = ONE LDG.128.
#define XYZ4_CAP 131072
__device__ float4 g_xyz4[XYZ4_CAP];

// Vectorized repack: thread j handles nodes 4j..4j+3 via 3 float4 loads.
__global__ __launch_bounds__(256)
void repack_xyz4_kernel(const float4* __restrict__ xyz4, int N4, int N)
{
    int j = blockIdx.x * blockDim.x + threadIdx.x;
    if (j < N4) {
        float4 f0 = xyz4[3*j + 0];   // x0 y0 z0 x1
        float4 f1 = xyz4[3*j + 1];   // y1 z1 x2 y2
        float4 f2 = xyz4[3*j + 2];   // z2 x3 y3 z3
        g_xyz4[4*j + 0] = make_float4(f0.x, f0.y, f0.z, 0.0f);
        g_xyz4[4*j + 1] = make_float4(f0.w, f1.x, f1.y, 0.0f);
        g_xyz4[4*j + 2] = make_float4(f1.z, f1.w, f2.x, 0.0f);
        g_xyz4[4*j + 3] = make_float4(f2.y, f2.z, f2.w, 0.0f);
    } else if (j == N4) {
        const float* xyz = (const float*)xyz4;
        for (int i = 4 * N4; i < N; i++)
            g_xyz4[i] = make_float4(xyz[3*i+0], xyz[3*i+1], xyz[3*i+2], 0.0f);
    }
}

// Streaming (evict-first) ops: outputs are written once and never re-read,
// so keep them from evicting the L2-resident xyz4 table. Same for the
// read-once src/dst index streams.
__device__ __forceinline__ void store_cs(float* p, float v)
{
    asm volatile("st.global.cs.f32 [%0], %1;" :: "l"(p), "f"(v) : "memory");
}
__device__ __forceinline__ int load_idx_cs(const int* p)
{
    int v;
    asm volatile("ld.global.cs.s32 %0, [%1];" : "=r"(v) : "l"(p));
    return v;
}

__device__ __forceinline__ void edge_math(float4 a, float4 b,
                                          float cx, float cy, float cz,
                                          float& vx, float& vy, float& vz,
                                          float& dis)
{
    float dx = a.x - b.x, dy = a.y - b.y, dz = a.z - b.z;
    float ax = fabsf(dx), ay = fabsf(dy), az = fabsf(dz);

    float mx = fminf(cx - ax, ax);
    float my = fminf(cy - ay, ay);
    float mz = fminf(cz - az, az);

    float k2x = (fabsf(mx) == ax) ? 1.0f : -1.0f;
    float k2y = (fabsf(my) == ay) ? 1.0f : -1.0f;
    float k2z = (fabsf(mz) == az) ? 1.0f : -1.0f;

    float sx = (dx + EPS_SIGN >= 0.0f) ? 1.0f : -1.0f;
    float sy = (dy + EPS_SIGN >= 0.0f) ? 1.0f : -1.0f;
    float sz = (dz + EPS_SIGN >= 0.0f) ? 1.0f : -1.0f;

    vx = mx * (k2x * sx);
    vy = my * (k2y * sy);
    vz = mz * (k2z * sz);

    float ex = dx + EPS_NORM, ey = dy + EPS_NORM, ez = dz + EPS_NORM;
    dis = sqrtf(ex*ex + ey*ey + ez*ez);
}

// R6 geometry (best measured): 2 edges/thread warp-strided (e, e+32),
// shuffle-coalesced vec stores. Only change vs R6: streaming (.cs) output
// stores + index loads so the xyz4 table stays resident in L2.
__global__ __launch_bounds__(256)
void edge_min_image_kernel(const int*   __restrict__ src,
                           const int*   __restrict__ dst,
                           const float* __restrict__ cell,
                           float* __restrict__ out_dis,
                           float* __restrict__ out_vec,
                           int E)
{
    int tid  = blockIdx.x * blockDim.x + threadIdx.x;
    int lane = threadIdx.x & 31;
    int base = ((tid >> 5) << 6);        // 64 edges per warp
    if (base >= E) return;

    const float cx = __ldg(&cell[0]);
    const float cy = __ldg(&cell[1]);
    const float cz = __ldg(&cell[2]);

    int e0 = base + lane;
    int e1 = base + 32 + lane;

    if (base + 64 <= E) {
        int s0 = load_idx_cs(src + e0);
        int s1 = load_idx_cs(src + e1);
        int d0 = load_idx_cs(dst + e0);
        int d1 = load_idx_cs(dst + e1);

        float4 a0 = __ldg(&g_xyz4[s0]);
        float4 a1 = __ldg(&g_xyz4[s1]);
        float4 b0 = __ldg(&g_xyz4[d0]);
        float4 b1 = __ldg(&g_xyz4[d1]);

        float vx0, vy0, vz0, dis0, vx1, vy1, vz1, dis1;
        edge_math(a0, b0, cx, cy, cz, vx0, vy0, vz0, dis0);
        edge_math(a1, b1, cx, cy, cz, vx1, vy1, vz1, dis1);

        store_cs(out_dis + e0, dis0);
        store_cs(out_dis + e1, dis1);

        float* bp = out_vec + 3 * base;  // 192-float span
        #pragma unroll
        for (int p = 0; p < 3; p++) {    // slot 0: floats [0,96)
            int g  = p * 32 + lane;
            int sl = g / 3;
            int c  = g - 3 * sl;
            float t0 = __shfl_sync(0xffffffffu, vx0, sl);
            float t1 = __shfl_sync(0xffffffffu, vy0, sl);
            float t2 = __shfl_sync(0xffffffffu, vz0, sl);
            store_cs(bp + g, (c == 0) ? t0 : ((c == 1) ? t1 : t2));
        }
        #pragma unroll
        for (int p = 0; p < 3; p++) {    // slot 1: floats [96,192)
            int g  = p * 32 + lane;
            int sl = g / 3;
            int c  = g - 3 * sl;
            float t0 = __shfl_sync(0xffffffffu, vx1, sl);
            float t1 = __shfl_sync(0xffffffffu, vy1, sl);
            float t2 = __shfl_sync(0xffffffffu, vz1, sl);
            store_cs(bp + 96 + g, (c == 0) ? t0 : ((c == 1) ? t1 : t2));
        }
    } else {
        // tail warp: per-edge scalar
        #pragma unroll
        for (int k = 0; k < 2; k++) {
            int e = base + 32 * k + lane;
            if (e < E) {
                float4 a = __ldg(&g_xyz4[__ldg(&src[e])]);
                float4 b = __ldg(&g_xyz4[__ldg(&dst[e])]);
                float vx, vy, vz, dis;
                edge_math(a, b, cx, cy, cz, vx, vy, vz, dis);
                out_dis[e] = dis;
                float* vp = out_vec + 3 * e;
                vp[0] = vx; vp[1] = vy; vp[2] = vz;
            }
        }
    }
}

// Fallback (N > scratch capacity): scalar-gather path, always correct.
__global__ __launch_bounds__(256)
void edge_min_image_fallback(const float* __restrict__ xyz,
                             const int*   __restrict__ src,
                             const int*   __restrict__ dst,
                             const float* __restrict__ cell,
                             float* __restrict__ out_dis,
                             float* __restrict__ out_vec,
                             int E)
{
    const float cx = __ldg(&cell[0]);
    const float cy = __ldg(&cell[1]);
    const float cz = __ldg(&cell[2]);

    int e = blockIdx.x * blockDim.x + threadIdx.x;
    if (e >= E) return;

    int si = src[e], di = dst[e];
    float dx = xyz[3*si+0] - xyz[3*di+0];
    float dy = xyz[3*si+1] - xyz[3*di+1];
    float dz = xyz[3*si+2] - xyz[3*di+2];

    float ax = fabsf(dx), ay = fabsf(dy), az = fabsf(dz);
    float mx = fminf(cx - ax, ax);
    float my = fminf(cy - ay, ay);
    float mz = fminf(cz - az, az);
    float k2x = (fabsf(mx) == ax) ? 1.0f : -1.0f;
    float k2y = (fabsf(my) == ay) ? 1.0f : -1.0f;
    float k2z = (fabsf(mz) == az) ? 1.0f : -1.0f;
    float sx = (dx + EPS_SIGN >= 0.0f) ? 1.0f : -1.0f;
    float sy = (dy + EPS_SIGN >= 0.0f) ? 1.0f : -1.0f;
    float sz = (dz + EPS_SIGN >= 0.0f) ? 1.0f : -1.0f;

    out_vec[3*e+0] = mx * (k2x * sx);
    out_vec[3*e+1] = my * (k2y * sy);
    out_vec[3*e+2] = mz * (k2z * sz);

    float ex = dx + EPS_NORM, ey = dy + EPS_NORM, ez = dz + EPS_NORM;
    out_dis[e] = sqrtf(ex*ex + ey*ey + ez*ez);
}

extern "C" void kernel_launch(void* const* d_in, const int* in_sizes, int n_in,
                              void* d_out, int out_size)
{
    const float* xyz  = (const float*)d_in[0];
    const int*   src  = (const int*)  d_in[1];
    const int*   dst  = (const int*)  d_in[2];
    const float* cell = (const float*)d_in[3];

    int N = in_sizes[0] / 3;   // xyz rows
    int E = in_sizes[1];       // number of edges

    float* out_dis = (float*)d_out;   // [E]
    float* out_vec = out_dis + E;     // [E,3] row-major

    const int t = 256;
    if (N <= XYZ4_CAP) {
        int N4 = N / 4;
        int rthreads = N4 + 1;
        repack_xyz4_kernel<<<(rthreads + t - 1) / t, t>>>(
            (const float4*)xyz, N4, N);
        int warps  = (E + 63) / 64;      // 64 edges per warp
        int blocks = (warps + 7) / 8;    // 8 warps per block
        edge_min_image_kernel<<<blocks, t>>>(src, dst, cell,
                                             out_dis, out_vec, E);
    } else {
        edge_min_image_fallback<<<(E + t - 1) / t, t>>>(xyz, src, dst, cell,
                                                        out_dis, out_vec, E);
    }
}